// round 6
// baseline (speedup 1.0000x reference)
#include <cuda_runtime.h>
#include <cuda_fp16.h>
#include <cstdint>
#include <cstddef>

#define K_DIM 4096
#define N_DIM 11008
#define QROWS (K_DIM / 8)

#define BM 128
#define BN 128
#define BK 32
#define A_ST (BK + 8)   // 40 halves = 80B row stride (16B aligned)
#define B_ST (BN + 8)   // 136 halves = 272B row stride (16B aligned)

// Scratch: dequantized weights [K, N] fp16 (90.2 MB) + x converted to fp16 (33.5 MB).
// NOTE: these are referenced ONLY from device code — taking their address in
// host code yields the host shadow (which GB300 ATS silently reads as zeros!).
__device__ __half g_W[(size_t)K_DIM * N_DIM];
__device__ __half g_X[(size_t)4096 * K_DIM];

// ---------------------------------------------------------------------------
// Kernel 0: convert x (float32 from the harness) -> fp16 in g_X.
// ---------------------------------------------------------------------------
__global__ void convert_x_kernel(const float* __restrict__ x, size_t n) {
    size_t i = ((size_t)blockIdx.x * blockDim.x + threadIdx.x) * 4;
    if (i >= n) return;
    float4 v = *reinterpret_cast<const float4*>(x + i);
    *reinterpret_cast<__half2*>(&g_X[i]) = __floats2half2_rn(v.x, v.y);
    *reinterpret_cast<__half2*>(&g_X[i + 2]) = __floats2half2_rn(v.z, v.w);
}

// ---------------------------------------------------------------------------
// Kernel 1: unpack int4 weights, subtract zeros, scale -> fp16 W in g_W.
// ---------------------------------------------------------------------------
__global__ void dequant_kernel(const int* __restrict__ qw,
                               const int* __restrict__ qz,
                               const float* __restrict__ sc) {
    int c = blockIdx.x * blockDim.x + threadIdx.x;
    if (c >= N_DIM) return;
    int kk = blockIdx.y;                       // 0..511 packed K rows
    int packed = qw[kk * N_DIM + c];
    int g = kk >> 4;                           // group = (kk*8)/128
    int zp = qz[g * (N_DIM / 8) + (c >> 3)];
    int z = (zp >> ((c & 7) * 4)) & 15;
    float s = sc[g * N_DIM + c];               // fp32 copy of an fp16 value (exact)
    size_t base = (size_t)kk * 8 * N_DIM + c;
#pragma unroll
    for (int i = 0; i < 8; i++) {
        int q = (packed >> (i * 4)) & 15;
        g_W[base + (size_t)i * N_DIM] = __float2half((float)(q - z) * s);
    }
}

// ---------------------------------------------------------------------------
// Kernel 2: fp16 GEMM  C[M,N] = g_X[M,K] * g_W[K,N] + bias, fp32 accumulate.
// 128x128x32 CTA tile, 8 warps, mma.sync m16n8k16, cp.async double buffered.
// ---------------------------------------------------------------------------
__device__ __forceinline__ void cp16(uint32_t s, const void* g) {
    asm volatile("cp.async.cg.shared.global [%0], [%1], 16;\n" ::"r"(s), "l"(g) : "memory");
}

__device__ __forceinline__ void issue_tile(int tid, uint32_t sa, uint32_t sb,
                                           const __half* Ag, const __half* Bg,
                                           int k0) {
#pragma unroll
    for (int t = 0; t < 2; t++) {
        int ci = tid + t * 256;
        // A tile: 128 rows x 32 halves -> 512 16B chunks
        int ar = ci >> 2, ac = (ci & 3) << 3;
        cp16(sa + (ar * A_ST + ac) * 2, Ag + (size_t)ar * K_DIM + k0 + ac);
        // B tile: 32 rows x 128 halves -> 512 16B chunks
        int br = ci >> 4, bc = (ci & 15) << 3;
        cp16(sb + (br * B_ST + bc) * 2, Bg + (size_t)(k0 + br) * N_DIM + bc);
    }
    asm volatile("cp.async.commit_group;\n" ::: "memory");
}

__global__ __launch_bounds__(256) void gemm_kernel(const float* __restrict__ bias,
                                                   float* __restrict__ C) {
    __shared__ __align__(16) __half As[2][BM * A_ST];
    __shared__ __align__(16) __half Bs[2][BK * B_ST];

    const int tid = threadIdx.x;
    const int lane = tid & 31;
    const int warp = tid >> 5;
    const int wm = warp >> 2;   // 0..1
    const int wn = warp & 3;    // 0..3
    const int bm = blockIdx.y;
    const int bn = blockIdx.x;

    const __half* Ag = g_X + (size_t)bm * BM * K_DIM;   // device-side symbol ref
    const __half* Bg = g_W + (size_t)bn * BN;

    uint32_t sA[2] = {(uint32_t)__cvta_generic_to_shared(As[0]),
                      (uint32_t)__cvta_generic_to_shared(As[1])};
    uint32_t sB[2] = {(uint32_t)__cvta_generic_to_shared(Bs[0]),
                      (uint32_t)__cvta_generic_to_shared(Bs[1])};

    float acc[4][4][4];
#pragma unroll
    for (int i = 0; i < 4; i++)
#pragma unroll
        for (int j = 0; j < 4; j++)
#pragma unroll
            for (int k = 0; k < 4; k++) acc[i][j][k] = 0.0f;

    const int NK = K_DIM / BK;  // 128
    issue_tile(tid, sA[0], sB[0], Ag, Bg, 0);

    for (int kt = 0; kt < NK; kt++) {
        asm volatile("cp.async.wait_group 0;\n" ::: "memory");
        __syncthreads();
        int cur = kt & 1;
        if (kt + 1 < NK)
            issue_tile(tid, sA[cur ^ 1], sB[cur ^ 1], Ag, Bg, (kt + 1) * BK);

#pragma unroll
        for (int ks = 0; ks < 2; ks++) {
            uint32_t af[4][4];
#pragma unroll
            for (int mi = 0; mi < 4; mi++) {
                int m = wm * 64 + mi * 16 + (lane & 15);
                int kc = ks * 16 + ((lane >> 4) << 3);
                uint32_t addr = sA[cur] + (m * A_ST + kc) * 2;
                asm volatile(
                    "ldmatrix.sync.aligned.m8n8.x4.shared.b16 {%0,%1,%2,%3}, [%4];\n"
                    : "=r"(af[mi][0]), "=r"(af[mi][1]), "=r"(af[mi][2]), "=r"(af[mi][3])
                    : "r"(addr));
            }
            uint32_t bf[2][4];
#pragma unroll
            for (int nj = 0; nj < 2; nj++) {
                int kr = ks * 16 + (lane & 15);
                int n = wn * 32 + nj * 16 + ((lane >> 4) << 3);
                uint32_t addr = sB[cur] + (kr * B_ST + n) * 2;
                asm volatile(
                    "ldmatrix.sync.aligned.m8n8.x4.trans.shared.b16 {%0,%1,%2,%3}, [%4];\n"
                    : "=r"(bf[nj][0]), "=r"(bf[nj][1]), "=r"(bf[nj][2]), "=r"(bf[nj][3])
                    : "r"(addr));
            }
#pragma unroll
            for (int mi = 0; mi < 4; mi++)
#pragma unroll
                for (int ni = 0; ni < 4; ni++) {
                    uint32_t b0 = bf[ni >> 1][(ni & 1) * 2];
                    uint32_t b1 = bf[ni >> 1][(ni & 1) * 2 + 1];
                    asm volatile(
                        "mma.sync.aligned.m16n8k16.row.col.f32.f16.f16.f32 "
                        "{%0,%1,%2,%3}, {%4,%5,%6,%7}, {%8,%9}, {%0,%1,%2,%3};\n"
                        : "+f"(acc[mi][ni][0]), "+f"(acc[mi][ni][1]),
                          "+f"(acc[mi][ni][2]), "+f"(acc[mi][ni][3])
                        : "r"(af[mi][0]), "r"(af[mi][1]), "r"(af[mi][2]), "r"(af[mi][3]),
                          "r"(b0), "r"(b1));
                }
        }
    }

    // Epilogue: emulate reference: fp16(acc) + fp16(bias) in fp16, widen to fp32.
#pragma unroll
    for (int mi = 0; mi < 4; mi++) {
        int r = bm * BM + wm * 64 + mi * 16 + (lane >> 2);
#pragma unroll
        for (int ni = 0; ni < 4; ni++) {
            int col = bn * BN + wn * 32 + ni * 8 + (lane & 3) * 2;
            __half b0 = __float2half_rn(bias[col]);
            __half b1 = __float2half_rn(bias[col + 1]);
            float2 v0, v1;
            v0.x = __half2float(__hadd(__float2half_rn(acc[mi][ni][0]), b0));
            v0.y = __half2float(__hadd(__float2half_rn(acc[mi][ni][1]), b1));
            v1.x = __half2float(__hadd(__float2half_rn(acc[mi][ni][2]), b0));
            v1.y = __half2float(__hadd(__float2half_rn(acc[mi][ni][3]), b1));
            *reinterpret_cast<float2*>(C + (size_t)r * N_DIM + col) = v0;
            *reinterpret_cast<float2*>(C + (size_t)(r + 8) * N_DIM + col) = v1;
        }
    }
}

extern "C" void kernel_launch(void* const* d_in, const int* in_sizes, int n_in,
                              void* d_out, int out_size) {
    // Resolve inputs by ELEMENT COUNT (robust to metadata ordering):
    //   x: 16777216   qweight: 5636096   qzeros: 44032   scales: 352256   bias: 11008
    const float* x = nullptr;
    const int* qw = nullptr;
    const int* qz = nullptr;
    const float* sc = nullptr;
    const float* bias = nullptr;
    size_t x_elems = 0;
    for (int i = 0; i < n_in; i++) {
        int sz = in_sizes[i];
        if (sz == QROWS * N_DIM) qw = (const int*)d_in[i];
        else if (sz == 32 * (N_DIM / 8)) qz = (const int*)d_in[i];
        else if (sz == 32 * N_DIM) sc = (const float*)d_in[i];
        else if (sz == N_DIM) bias = (const float*)d_in[i];
        else if (sz == 16777216) { x = (const float*)d_in[i]; x_elems = (size_t)sz; }
    }
    float* out = (float*)d_out;

    int M = (int)(x_elems / K_DIM);  // 4096

    convert_x_kernel<<<(unsigned)((x_elems / 4 + 255) / 256), 256>>>(x, x_elems);

    dim3 dq_grid((N_DIM + 255) / 256, QROWS);
    dequant_kernel<<<dq_grid, 256>>>(qw, qz, sc);

    dim3 g_grid(N_DIM / BN, M / BM);
    gemm_kernel<<<g_grid, 256>>>(bias, out);
}